// round 6
// baseline (speedup 1.0000x reference)
#include <cuda_runtime.h>
#include <cuda_fp16.h>
#include <math_constants.h>
#include <cstdint>

#define B_   16
#define L_   18
#define SQ_  256
#define H_   2560
#define R_   256
#define D_   2048
#define C_   32
#define TOPK_ 16

// ---------------- scratch (no allocs allowed) ----------------
__device__ unsigned int g_qenc[B_ * L_ * R_];
__device__ float        g_qvec[B_ * L_ * R_];
__device__ float        g_scores[B_ * D_];
__device__ uint32_t     g_wsplit[(size_t)L_ * 80 * 8192];

__device__ __forceinline__ unsigned enc_f(float f) {
    unsigned u = __float_as_uint(f);
    return (u & 0x80000000u) ? ~u : (u | 0x80000000u);
}
__device__ __forceinline__ float dec_f(unsigned u) {
    unsigned b = (u & 0x80000000u) ? (u & 0x7FFFFFFFu) : ~u;
    return __uint_as_float(b);
}

__device__ __forceinline__ void split2(float x, float y, uint32_t& m, uint32_t& c) {
    __half hx = __float2half_rn(x);
    __half hy = __float2half_rn(y);
    float rx = x - __half2float(hx);
    float ry = y - __half2float(hy);
    __half2 hm = __halves2half2(hx, hy);
    __half2 hc = __halves2half2(__float2half_rn(rx), __float2half_rn(ry));
    m = *reinterpret_cast<uint32_t*>(&hm);
    c = *reinterpret_cast<uint32_t*>(&hc);
}

#define MMA_F16(Cv, Av, Bv)                                                    \
    asm volatile("mma.sync.aligned.m16n8k16.row.col.f32.f16.f16.f32 "          \
                 "{%0,%1,%2,%3}, {%4,%5,%6,%7}, {%8,%9}, {%0,%1,%2,%3};"       \
                 : "+f"(Cv[0]), "+f"(Cv[1]), "+f"(Cv[2]), "+f"(Cv[3])          \
                 : "r"(Av[0]), "r"(Av[1]), "r"(Av[2]), "r"(Av[3]),             \
                   "r"(Bv[0]), "r"(Bv[1]))

__device__ __forceinline__ uint32_t smem_u32(const void* p) {
    uint32_t a;
    asm("{ .reg .u64 t; cvta.to.shared.u64 t, %1; cvt.u32.u64 %0, t; }"
        : "=r"(a) : "l"(p));
    return a;
}
__device__ __forceinline__ void cpa16(uint32_t saddr, const void* g) {
    asm volatile("cp.async.cg.shared.global [%0], [%1], 16;" :: "r"(saddr), "l"(g));
}
__device__ __forceinline__ void cpa_commit() { asm volatile("cp.async.commit_group;"); }
template <int N>
__device__ __forceinline__ void cpa_wait() {
    asm volatile("cp.async.wait_group %0;" :: "n"(N) : "memory");
}

// ---------------------------------------------------------------------------
__global__ void init_kernel() {
    g_qenc[blockIdx.x * 256 + threadIdx.x] = 0u;
}

// ---------------------------------------------------------------------------
// wprep: split wq*64 into fp16 main/corr in B-fragment order.
// ---------------------------------------------------------------------------
__global__ __launch_bounds__(256) void wprep_kernel(const float* __restrict__ wq) {
    const int lt = blockIdx.x;
    const int l = lt / 80, t = lt % 80;
    const int tid = threadIdx.x;
    uint32_t* dst = g_wsplit + (size_t)lt * 8192;
    const float* src = wq + (size_t)l * R_ * H_ + t * 32;
#pragma unroll
    for (int i = 0; i < 8; i++) {
        int ch = tid + i * 256;
        int r  = ch >> 3;
        int k4 = (ch & 7) << 2;
        float4 v = *(const float4*)(src + (size_t)r * H_ + k4);
        v.x *= 64.f; v.y *= 64.f; v.z *= 64.f; v.w *= 64.f;
        int ntg = r >> 3, g = r & 7;
        int kc = k4 >> 4, kk16 = k4 & 15;
        int tq = (kk16 >> 1) & 3, khalf = kk16 >> 3;
        uint32_t m0, c0, m1, c1;
        split2(v.x, v.y, m0, c0);
        split2(v.z, v.w, m1, c1);
        int base = (ntg * 2 + kc) * 32 + g * 4;
        dst[(base + tq) * 2 + khalf]            = m0;
        dst[4096 + (base + tq) * 2 + khalf]     = c0;
        dst[(base + tq + 1) * 2 + khalf]        = m1;
        dst[4096 + (base + tq + 1) * 2 + khalf] = c1;
    }
}

// ---------------------------------------------------------------------------
// proj_kernel: unchanged from R5 (fp16 3-term split mma GEMM, 128s x 256r)
// ---------------------------------------------------------------------------
#define PSTG_U32  12288
#define PROJ_SMEM (2 * PSTG_U32 * 4)

__global__ __launch_bounds__(256)
void proj_kernel(const float* __restrict__ qhs) {
    extern __shared__ uint32_t sm[];
    const int tid  = threadIdx.x;
    const int lane = tid & 31;
    const int warp = tid >> 5;
    const int wm   = warp >> 2;
    const int wn   = warp & 3;

    const int bl = blockIdx.x;
    const int sT = blockIdx.y;
    const int l  = bl % L_;

    const float* Ag = qhs + ((size_t)bl * SQ_ + (size_t)sT * 128) * H_;
    const uint32_t* Wg = g_wsplit + (size_t)l * 80 * 8192;
    const uint32_t sbase = smem_u32(sm);

    float acc[4][8][4];
#pragma unroll
    for (int i = 0; i < 4; i++)
#pragma unroll
        for (int j = 0; j < 8; j++)
#pragma unroll
            for (int k = 0; k < 4; k++) acc[i][j][k] = 0.0f;

    float4 pa[4];

    auto ldA = [&](int t) {
#pragma unroll
        for (int i = 0; i < 4; i++) {
            int ch = tid + i * 256;
            int row = ch >> 3;
            int k4 = (ch & 7) << 2;
            pa[i] = *(const float4*)(Ag + (size_t)row * H_ + t * 32 + k4);
        }
    };
    auto stA = [&](int s) {
        uint32_t* base = sm + s * PSTG_U32;
#pragma unroll
        for (int i = 0; i < 4; i++) {
            int ch = tid + i * 256;
            int row = ch >> 3;
            int k4 = (ch & 7) << 2;
            int mt = row >> 4, r16 = row & 15;
            int g = r16 & 7, half = r16 >> 3;
            int kc = k4 >> 4, kk16 = k4 & 15;
            int tq = (kk16 >> 1) & 3, khalf = kk16 >> 3;
            int j = half + 2 * khalf;
            uint32_t m0, c0, m1, c1;
            split2(pa[i].x, pa[i].y, m0, c0);
            split2(pa[i].z, pa[i].w, m1, c1);
            int ab = (mt * 2 + kc) * 32 + g * 4;
            base[(ab + tq) * 4 + j]            = m0;
            base[2048 + (ab + tq) * 4 + j]     = c0;
            base[(ab + tq + 1) * 4 + j]        = m1;
            base[2048 + (ab + tq + 1) * 4 + j] = c1;
        }
    };
    auto prefB = [&](int t, int s) {
        uint32_t dstb = sbase + (s * PSTG_U32 + 4096) * 4;
        const uint32_t* gsrc = Wg + (size_t)t * 8192;
#pragma unroll
        for (int i = 0; i < 8; i++) {
            int off = (tid + i * 256) * 4;
            cpa16(dstb + off * 4, gsrc + off);
        }
        cpa_commit();
    };

    prefB(0, 0);
    ldA(0);
    stA(0);
    cpa_wait<0>();
    __syncthreads();

    for (int t = 0; t < 80; t++) {
        const int s = t & 1;
        if (t < 79) { prefB(t + 1, s ^ 1); ldA(t + 1); }

        const uint32_t* A_ = sm + s * PSTG_U32;
        const uint32_t* Bm = A_ + 4096;
        const uint32_t* Bc = A_ + 8192;

#pragma unroll
        for (int kc = 0; kc < 2; kc++) {
            uint32_t ah[4][4], ac[4][4];
#pragma unroll
            for (int mt = 0; mt < 4; mt++) {
                int mtg = wm * 4 + mt;
                *(uint4*)ah[mt] = *(const uint4*)(A_ + ((mtg * 2 + kc) * 32 + lane) * 4);
                *(uint4*)ac[mt] = *(const uint4*)(A_ + 2048 + ((mtg * 2 + kc) * 32 + lane) * 4);
            }
#pragma unroll
            for (int nt = 0; nt < 8; nt++) {
                int ntg = wn * 8 + nt;
                uint2 bm = *(const uint2*)(Bm + ((ntg * 2 + kc) * 32 + lane) * 2);
                uint2 bc = *(const uint2*)(Bc + ((ntg * 2 + kc) * 32 + lane) * 2);
                uint32_t bmv[2] = { bm.x, bm.y };
                uint32_t bcv[2] = { bc.x, bc.y };
#pragma unroll
                for (int mt = 0; mt < 4; mt++) MMA_F16(acc[mt][nt], ah[mt], bmv);
#pragma unroll
                for (int mt = 0; mt < 4; mt++) MMA_F16(acc[mt][nt], ah[mt], bcv);
#pragma unroll
                for (int mt = 0; mt < 4; mt++) MMA_F16(acc[mt][nt], ac[mt], bmv);
            }
        }

        if (t < 79) { stA(s ^ 1); cpa_wait<0>(); }
        __syncthreads();
    }

    unsigned* qe = g_qenc + (size_t)bl * R_;
#pragma unroll
    for (int nt = 0; nt < 8; nt++) {
        float v0 = -CUDART_INF_F, v1 = -CUDART_INF_F;
#pragma unroll
        for (int mt = 0; mt < 4; mt++) {
            v0 = fmaxf(v0, fmaxf(acc[mt][nt][0], acc[mt][nt][2]));
            v1 = fmaxf(v1, fmaxf(acc[mt][nt][1], acc[mt][nt][3]));
        }
#pragma unroll
        for (int o = 4; o < 32; o <<= 1) {
            v0 = fmaxf(v0, __shfl_xor_sync(0xffffffffu, v0, o));
            v1 = fmaxf(v1, __shfl_xor_sync(0xffffffffu, v1, o));
        }
        if (lane < 4) {
            int col = (wn * 8 + nt) * 8 + lane * 2;
            atomicMax(&qe[col],     enc_f(v0));
            atomicMax(&qe[col + 1], enc_f(v1));
        }
    }
}

// ---------------------------------------------------------------------------
// norm_kernel
// ---------------------------------------------------------------------------
__global__ void norm_kernel() {
    const int blk = blockIdx.x;
    const int t = threadIdx.x;
    float v = dec_f(g_qenc[blk * R_ + t]);
    float s = v * v;
#pragma unroll
    for (int o = 16; o > 0; o >>= 1) s += __shfl_xor_sync(0xffffffffu, s, o);
    __shared__ float ws[8];
    if ((t & 31) == 0) ws[t >> 5] = s;
    __syncthreads();
    float tot = 0.0f;
#pragma unroll
    for (int i = 0; i < 8; i++) tot += ws[i];
    g_qvec[blk * R_ + t] = v / fmaxf(sqrtf(tot), 1e-12f);
}

// ---------------------------------------------------------------------------
// doc_kernel v3: 4c x 4b register outer-product per thread, r-split over
// 8 lanes. Per thread-iter: 8 LDS.128 feed 80 FMA (FMA-bound, was crossbar).
// Mapping: warp w: bq=w>>1, cq_base=(w&1)*4; lane: hi=lane>>3 -> cq=cq_base+hi,
// rs=lane&7 -> r4 slices {rs, rs+8, ..., rs+56}.
// ---------------------------------------------------------------------------
#define K_STAGE_F  (C_ * 260)
#define Q_STAGE_F  (B_ * 260)
#define STAGE_F    (K_STAGE_F + Q_STAGE_F)
#define DOC_SMEM   (2 * STAGE_F * 4 + 512)

__global__ __launch_bounds__(256, 2)
void doc_kernel(const float* __restrict__ dkeys) {
    extern __shared__ char dsm[];
    const int d = blockIdx.x;
    const int tid = threadIdx.x;
    const int w = tid >> 5;
    const int lane = tid & 31;
    const int bq = w >> 1;                  // 0..3  -> b = bq*4 + j
    const int cq = (w & 1) * 4 + (lane >> 3);   // 0..7 -> c = cq*4 + i
    const int rs = lane & 7;                // r-slice

    float* wmax_s = (float*)(dsm + 2 * STAGE_F * 4);  // [8 warps][4 j]
    const uint32_t sb = smem_u32(dsm);

    auto stage = [&](int s, int l) {
        const float* ksrc = dkeys + (((size_t)d * L_ + l) * C_) * R_;
        uint32_t kdst = sb + s * (STAGE_F * 4);
#pragma unroll
        for (int i = 0; i < 8; i++) {
            int id = tid + i * 256;
            int cc = id >> 6, off = id & 63;
            cpa16(kdst + (cc * 260 + off * 4) * 4, ksrc + id * 4);
        }
        uint32_t qdst = kdst + K_STAGE_F * 4;
#pragma unroll
        for (int i = 0; i < 4; i++) {
            int id = tid + i * 256;
            int bb = id >> 6, off = id & 63;
            cpa16(qdst + (bb * 260 + off * 4) * 4, g_qvec + (bb * L_ + l) * R_ + off * 4);
        }
        cpa_commit();
    };

    stage(0, 0);

    float acc[4] = {0.f, 0.f, 0.f, 0.f};

    for (int l = 0; l < L_; l++) {
        const int s = l & 1;
        if (l < L_ - 1) stage(s ^ 1, l + 1);
        if (l < L_ - 1) cpa_wait<1>(); else cpa_wait<0>();
        __syncthreads();

        const float* kb = (const float*)(dsm + s * (STAGE_F * 4));
        const float* qb = kb + K_STAGE_F;

        float dot[4][4], nn[4];
#pragma unroll
        for (int i = 0; i < 4; i++) {
            nn[i] = 0.f;
#pragma unroll
            for (int j = 0; j < 4; j++) dot[i][j] = 0.f;
        }

#pragma unroll
        for (int it = 0; it < 8; it++) {
            const int r4 = it * 8 + rs;
            float4 kv[4], qv[4];
#pragma unroll
            for (int i = 0; i < 4; i++)
                kv[i] = *(const float4*)(kb + (cq * 4 + i) * 260 + r4 * 4);
#pragma unroll
            for (int j = 0; j < 4; j++)
                qv[j] = *(const float4*)(qb + (bq * 4 + j) * 260 + r4 * 4);
#pragma unroll
            for (int i = 0; i < 4; i++) {
                nn[i] = fmaf(kv[i].x, kv[i].x, nn[i]);
                nn[i] = fmaf(kv[i].y, kv[i].y, nn[i]);
                nn[i] = fmaf(kv[i].z, kv[i].z, nn[i]);
                nn[i] = fmaf(kv[i].w, kv[i].w, nn[i]);
#pragma unroll
                for (int j = 0; j < 4; j++) {
                    dot[i][j] = fmaf(kv[i].x, qv[j].x, dot[i][j]);
                    dot[i][j] = fmaf(kv[i].y, qv[j].y, dot[i][j]);
                    dot[i][j] = fmaf(kv[i].z, qv[j].z, dot[i][j]);
                    dot[i][j] = fmaf(kv[i].w, qv[j].w, dot[i][j]);
                }
            }
        }

        // reduce over the 8 r-slices (lanes differing in bits 0..2)
#pragma unroll
        for (int o = 1; o < 8; o <<= 1) {
#pragma unroll
            for (int i = 0; i < 4; i++) {
                nn[i] += __shfl_xor_sync(0xffffffffu, nn[i], o);
#pragma unroll
                for (int j = 0; j < 4; j++)
                    dot[i][j] += __shfl_xor_sync(0xffffffffu, dot[i][j], o);
            }
        }

        // normalize + max over this thread's 4 c, then over warp's cq set
        float m[4];
#pragma unroll
        for (int j = 0; j < 4; j++) m[j] = -CUDART_INF_F;
#pragma unroll
        for (int i = 0; i < 4; i++) {
            float inv = 1.0f / fmaxf(sqrtf(nn[i]), 1e-12f);
#pragma unroll
            for (int j = 0; j < 4; j++)
                m[j] = fmaxf(m[j], dot[i][j] * inv);
        }
#pragma unroll
        for (int j = 0; j < 4; j++) {
            m[j] = fmaxf(m[j], __shfl_xor_sync(0xffffffffu, m[j], 8));
            m[j] = fmaxf(m[j], __shfl_xor_sync(0xffffffffu, m[j], 16));
        }
        if (lane == 0) {
#pragma unroll
            for (int j = 0; j < 4; j++) wmax_s[w * 4 + j] = m[j];
        }
        __syncthreads();
        if ((w & 1) == 0) {
#pragma unroll
            for (int j = 0; j < 4; j++)
                acc[j] += fmaxf(wmax_s[w * 4 + j], wmax_s[(w + 1) * 4 + j]);
        }
        __syncthreads();
    }

    if ((w & 1) == 0 && lane == 0) {
#pragma unroll
        for (int j = 0; j < 4; j++)
            g_scores[(bq * 4 + j) * D_ + d] = acc[j] * (1.0f / (float)L_);
    }
}

// ---------------------------------------------------------------------------
// topk_kernel
// ---------------------------------------------------------------------------
__global__ void topk_kernel(float* __restrict__ out, int half) {
    const int b = blockIdx.x;
    const int t = threadIdx.x;
    __shared__ float sv[D_];
    __shared__ float rv[256];
    __shared__ int   ri[256];

    for (int i = t; i < D_; i += 256) sv[i] = g_scores[b * D_ + i];
    __syncthreads();

    for (int k = 0; k < TOPK_; k++) {
        float bv = -CUDART_INF_F;
        int   bi = 0x7fffffff;
        for (int i = t; i < D_; i += 256) {
            float v = sv[i];
            if (v > bv || (v == bv && i < bi)) { bv = v; bi = i; }
        }
        rv[t] = bv; ri[t] = bi;
        __syncthreads();
        for (int s = 128; s > 0; s >>= 1) {
            if (t < s) {
                float ov = rv[t + s]; int oi = ri[t + s];
                if (ov > rv[t] || (ov == rv[t] && oi < ri[t])) { rv[t] = ov; ri[t] = oi; }
            }
            __syncthreads();
        }
        if (t == 0) {
            out[b * TOPK_ + k]        = rv[0];
            out[half + b * TOPK_ + k] = (float)ri[0];
            sv[ri[0]] = -CUDART_INF_F;
        }
        __syncthreads();
    }
}

extern "C" void kernel_launch(void* const* d_in, const int* in_sizes, int n_in,
                              void* d_out, int out_size) {
    const float* qhs = (const float*)d_in[0];
    const float* wq  = (const float*)d_in[1];
    const float* dk  = (const float*)d_in[2];
    float* out = (float*)d_out;

    cudaFuncSetAttribute(proj_kernel, cudaFuncAttributeMaxDynamicSharedMemorySize, PROJ_SMEM);
    cudaFuncSetAttribute(doc_kernel,  cudaFuncAttributeMaxDynamicSharedMemorySize, DOC_SMEM);

    init_kernel<<<B_ * L_, 256>>>();
    wprep_kernel<<<L_ * 80, 256>>>(wq);
    dim3 gp(B_ * L_, 2);
    proj_kernel<<<gp, 256, PROJ_SMEM>>>(qhs);
    norm_kernel<<<B_ * L_, 256>>>();
    doc_kernel<<<D_, 256, DOC_SMEM>>>(dk);
    topk_kernel<<<B_, 256>>>(out, out_size / 2);
}